// round 1
// baseline (speedup 1.0000x reference)
#include <cuda_runtime.h>

#define NTOK   49
#define DIM    128
#define NH     4
#define HD     32
#define ROW    129      // padded row stride (floats) for token-major tiles
#define APAD   52       // padded row stride for attention scores
#define SCALE  0.17677669529663687f   // 32^-0.5

// shared-memory float offsets
#define OFF_XS   0                    // 49*129 = 6321
#define OFF_WS   6321                 // 64*129 = 8256 (weight chunk)
#define OFF_QS   14577                // 49*129
#define OFF_KS   20898
#define OFF_VS   27219
#define SMEM_FLOATS 33540             // 134160 bytes
// overlays (after the owners are dead, with __syncthreads between):
//   attn  -> [0, 10192)  (over xs+ws)       alive: phase2..phase4
//   ws2   -> [0,  8256)  (over attn)        alive: phase5
//   ov    -> qs region                       alive: phase4..phase5

__global__ __launch_bounds__(256, 1)
void wmsa_fused_kernel(const float* __restrict__ x,
                       const float* __restrict__ attn_mask,
                       const float* __restrict__ qkv_w,
                       const float* __restrict__ qkv_b,
                       const float* __restrict__ proj_w,
                       const float* __restrict__ proj_b,
                       const float* __restrict__ bias_table,
                       const int*   __restrict__ rel_idx,
                       float* __restrict__ out)
{
    extern __shared__ float sm[];
    const int tid = threadIdx.x;
    const int w   = blockIdx.x;

    float* xs   = sm + OFF_XS;
    float* ws   = sm + OFF_WS;
    float* qs   = sm + OFF_QS;
    float* ks   = sm + OFF_KS;
    float* vs   = sm + OFF_VS;
    float* attn = sm;          // overlay
    float* ws2  = sm;          // overlay
    float* ov   = qs;          // overlay

    // ---------------- phase 0: load x tile ----------------
    const float* xg = x + (size_t)w * (NTOK * DIM);
    for (int idx = tid; idx < NTOK * DIM; idx += 256) {
        int i = idx >> 7, c = idx & 127;
        xs[i * ROW + c] = xg[idx];
    }

    // ---------------- phase 1: QKV GEMM (49x128 @ 128x384) ----------------
    // thread tile: 4 cols x (3..4) rows;  cg = col group, rg = row group
    const int cg = tid & 15;
    const int rg = tid >> 4;
    const int nt = (rg == 0) ? 4 : 3;   // rows rg+16t < 49

    for (int cc = 0; cc < 6; ++cc) {
        __syncthreads();
        // stage 64x128 weight chunk (coalesced rows)
        for (int idx = tid; idx < 64 * 128; idx += 256) {
            int rr = idx >> 7, kk = idx & 127;
            ws[rr * ROW + kk] = qkv_w[(cc * 64 + rr) * DIM + kk];
        }
        __syncthreads();

        float acc[4][4];
        #pragma unroll
        for (int t = 0; t < 4; ++t)
            #pragma unroll
            for (int m = 0; m < 4; ++m) acc[t][m] = 0.f;

        #pragma unroll 4
        for (int k = 0; k < DIM; ++k) {
            float wv[4];
            #pragma unroll
            for (int m = 0; m < 4; ++m) wv[m] = ws[(cg * 4 + m) * ROW + k];
            #pragma unroll
            for (int t = 0; t < 4; ++t) {
                if (t < nt) {
                    float xv = xs[(rg + 16 * t) * ROW + k];
                    #pragma unroll
                    for (int m = 0; m < 4; ++m) acc[t][m] += xv * wv[m];
                }
            }
        }

        // epilogue: scatter to q/k/v (each 64-col chunk maps to exactly one)
        const int base_c = cc * 64;
        const int sel    = base_c >> 7;            // 0=q, 1=k, 2=v
        float* dst = (sel == 0) ? qs : ((sel == 1) ? ks : vs);
        for (int t = 0; t < nt; ++t) {
            int r = rg + 16 * t;
            #pragma unroll
            for (int m = 0; m < 4; ++m) {
                int cglob = base_c + cg * 4 + m;
                float v = acc[t][m] + qkv_b[cglob];
                if (sel == 0) v *= SCALE;
                dst[r * ROW + (cglob & 127)] = v;
            }
        }
    }
    __syncthreads();

    // ---------------- phase 2: attention scores + bias + mask ----------------
    const float* maskg = attn_mask + (size_t)(w & 63) * (NTOK * NTOK);
    for (int idx = tid; idx < NH * NTOK * NTOK; idx += 256) {
        int h   = idx / (NTOK * NTOK);
        int rem = idx - h * (NTOK * NTOK);
        int i   = rem / NTOK;
        int j   = rem - i * NTOK;
        const float* qrow = qs + i * ROW + h * HD;   // broadcast across lanes
        const float* krow = ks + j * ROW + h * HD;   // stride ROW=129: conflict-free
        float a = 0.f;
        #pragma unroll
        for (int d = 0; d < HD; ++d) a += qrow[d] * krow[d];
        int rel = rel_idx[rem];
        a += bias_table[rel * NH + h] + maskg[rem];
        attn[(h * NTOK + i) * APAD + j] = a;
    }
    __syncthreads();

    // ---------------- phase 3: softmax (one warp per row) ----------------
    {
        const int warp = tid >> 5, lane = tid & 31;
        for (int row = warp; row < NH * NTOK; row += 8) {
            float* ar = attn + row * APAD;
            float v0 = ar[lane];
            float v1 = (lane + 32 < NTOK) ? ar[lane + 32] : -INFINITY;
            float m = fmaxf(v0, v1);
            #pragma unroll
            for (int o = 16; o; o >>= 1) m = fmaxf(m, __shfl_xor_sync(0xffffffffu, m, o));
            float e0 = __expf(v0 - m);
            float e1 = (lane + 32 < NTOK) ? __expf(v1 - m) : 0.f;
            float s = e0 + e1;
            #pragma unroll
            for (int o = 16; o; o >>= 1) s += __shfl_xor_sync(0xffffffffu, s, o);
            float inv = 1.f / s;
            ar[lane] = e0 * inv;
            if (lane + 32 < NTOK) ar[lane + 32] = e1 * inv;
        }
    }
    __syncthreads();

    // ---------------- phase 4: attn @ v  -> ov (reuses qs region) ----------------
    for (int idx = tid; idx < NTOK * DIM; idx += 256) {
        int i = idx >> 7, c = idx & 127;
        int h = c >> 5;
        const float* ar   = attn + (h * NTOK + i) * APAD;  // broadcast
        const float* vcol = vs + c;                        // stride-1 across lanes
        float a = 0.f;
        #pragma unroll
        for (int j = 0; j < NTOK; ++j) a += ar[j] * vcol[j * ROW];
        ov[i * ROW + c] = a;
    }
    __syncthreads();

    // ---------------- phase 5: proj GEMM (49x128 @ 128x128) ----------------
    float* og = out + (size_t)w * (NTOK * DIM);
    for (int cc = 0; cc < 2; ++cc) {
        if (cc) __syncthreads();
        for (int idx = tid; idx < 64 * 128; idx += 256) {
            int rr = idx >> 7, kk = idx & 127;
            ws2[rr * ROW + kk] = proj_w[(cc * 64 + rr) * DIM + kk];
        }
        __syncthreads();

        float acc[4][4];
        #pragma unroll
        for (int t = 0; t < 4; ++t)
            #pragma unroll
            for (int m = 0; m < 4; ++m) acc[t][m] = 0.f;

        #pragma unroll 4
        for (int k = 0; k < DIM; ++k) {
            float wv[4];
            #pragma unroll
            for (int m = 0; m < 4; ++m) wv[m] = ws2[(cg * 4 + m) * ROW + k];
            #pragma unroll
            for (int t = 0; t < 4; ++t) {
                if (t < nt) {
                    float xv = ov[(rg + 16 * t) * ROW + k];
                    #pragma unroll
                    for (int m = 0; m < 4; ++m) acc[t][m] += xv * wv[m];
                }
            }
        }

        for (int t = 0; t < nt; ++t) {
            int r = rg + 16 * t;
            #pragma unroll
            for (int m = 0; m < 4; ++m) {
                int cglob = cc * 64 + cg * 4 + m;
                og[r * DIM + cglob] = acc[t][m] + proj_b[cglob];
            }
        }
    }
}

extern "C" void kernel_launch(void* const* d_in, const int* in_sizes, int n_in,
                              void* d_out, int out_size)
{
    const float* x          = (const float*)d_in[0];
    const float* attn_mask  = (const float*)d_in[1];
    const float* qkv_w      = (const float*)d_in[2];
    const float* qkv_b      = (const float*)d_in[3];
    const float* proj_w     = (const float*)d_in[4];
    const float* proj_b     = (const float*)d_in[5];
    const float* bias_table = (const float*)d_in[6];
    const int*   rel_idx    = (const int*)d_in[7];
    float* out = (float*)d_out;

    const int smem_bytes = SMEM_FLOATS * sizeof(float);   // 134160 B
    cudaFuncSetAttribute(wmsa_fused_kernel,
                         cudaFuncAttributeMaxDynamicSharedMemorySize, smem_bytes);

    const int n_windows = in_sizes[0] / (NTOK * DIM);     // 4096
    wmsa_fused_kernel<<<n_windows, 256, smem_bytes>>>(
        x, attn_mask, qkv_w, qkv_b, proj_w, proj_b, bias_table, rel_idx, out);
}

// round 2
// speedup vs baseline: 1.4046x; 1.4046x over previous
#include <cuda_runtime.h>

typedef unsigned long long ull;

#define NTOK   49
#define DIMC   128
#define ROWW   132          // padded row stride (floats), multiple of 4
#define APAD   52           // attn row stride
#define AHS    2600         // attn head stride = 50*52
#define SCALE  0.17677669529663687f

// SMEM float offsets
#define XS_ROWS 56
#define OFF_WS  7392                       // 56*132
#define OFF_QS  24288                      // + 128*132
#define OFF_KS  30756                      // + 49*132
#define OFF_VS  37224                      // + 49*132
#define SMEM_FLOATS 43824                  // + 50*132  -> 175296 bytes
// overlays: attn (4*2600=10400 floats) @ 0  (over xs+ws head; dead then)
//           ov   @ OFF_QS (over qs; dead after QK)

__device__ __forceinline__ void fma2(ull& d, ull a, ull b) {
    asm("fma.rn.f32x2 %0, %1, %2, %0;" : "+l"(d) : "l"(a), "l"(b));
}
__device__ __forceinline__ ull dup2(float x) {
    ull r; asm("mov.b64 %0, {%1, %1};" : "=l"(r) : "f"(x)); return r;
}
__device__ __forceinline__ float2 unpk(ull v) {
    float2 r; asm("mov.b64 {%0, %1}, %2;" : "=f"(r.x), "=f"(r.y) : "l"(v)); return r;
}

// GEMM core: rows rg+8t (t<7), cols cg+32m (m<4), K=128, f32x2 paired over k.
// src rows [0,56) readable; ws = weights [c][k] stride ROWW.
__device__ __forceinline__ void gemm_core(const float* __restrict__ src,
                                          const float* __restrict__ wsm,
                                          ull acc[7][4], int cg, int rg)
{
    #pragma unroll 2
    for (int kq = 0; kq < 32; ++kq) {
        const int k = kq * 4;
        ulonglong2 xv[7];
        #pragma unroll
        for (int t = 0; t < 7; ++t)
            xv[t] = *(const ulonglong2*)(src + (rg + 8 * t) * ROWW + k);
        #pragma unroll
        for (int m = 0; m < 4; ++m) {
            ulonglong2 wv = *(const ulonglong2*)(wsm + (cg + 32 * m) * ROWW + k);
            #pragma unroll
            for (int t = 0; t < 7; ++t) {
                fma2(acc[t][m], xv[t].x, wv.x);
                fma2(acc[t][m], xv[t].y, wv.y);
            }
        }
    }
}

__global__ __launch_bounds__(256, 1)
void wmsa_fused_kernel(const float* __restrict__ x,
                       const float* __restrict__ attn_mask,
                       const float* __restrict__ qkv_w,
                       const float* __restrict__ qkv_b,
                       const float* __restrict__ proj_w,
                       const float* __restrict__ proj_b,
                       const float* __restrict__ bias_table,
                       const int*   __restrict__ rel_idx,
                       float* __restrict__ out)
{
    extern __shared__ float sm[];
    const int tid = threadIdx.x;
    const int w   = blockIdx.x;

    float* xs   = sm;                 // 56 x 132 (rows >=49 only need to be readable)
    float* wsm  = sm + OFF_WS;        // 128 x 132
    float* qs   = sm + OFF_QS;        // 49 x 132
    float* ks   = sm + OFF_KS;
    float* vs   = sm + OFF_VS;        // 50 x 132 slot
    float* attn = sm;                 // overlay: 4 heads x 50 x 52
    float* ov   = sm + OFF_QS;        // overlay over qs

    const int cg = tid & 31;          // col group (4 cols: cg + 32m)
    const int rg = tid >> 5;          // row group = warp id (7 rows: rg + 8t)

    // ---------- phase 0: load x (49x128) into xs; zero pad rows ----------
    {
        const float* xg = x + (size_t)w * (NTOK * DIMC);
        for (int q4 = tid; q4 < NTOK * 32; q4 += 256) {     // 1568 float4s
            int i = q4 >> 5, c4 = q4 & 31;
            *(float4*)(xs + i * ROWW + 4 * c4) = *(const float4*)(xg + i * DIMC + 4 * c4);
        }
        for (int idx = tid; idx < 7 * ROWW; idx += 256)     // zero rows 49..55
            xs[49 * ROWW + idx] = 0.f;
    }

    // ---------- phase 1: QKV GEMM, 3 stages of 128 cols ----------
    for (int s = 0; s < 3; ++s) {
        __syncthreads();
        // stage weights: ws[c][k] = qkv_w[(128s+c)*128 + k]
        const float* wg = qkv_w + (size_t)s * 128 * DIMC;
        for (int q4 = tid; q4 < 128 * 32; q4 += 256) {
            int c = q4 >> 5, k4 = q4 & 31;
            *(float4*)(wsm + c * ROWW + 4 * k4) = *(const float4*)(wg + c * DIMC + 4 * k4);
        }
        __syncthreads();

        ull acc[7][4];
        #pragma unroll
        for (int t = 0; t < 7; ++t)
            #pragma unroll
            for (int m = 0; m < 4; ++m) acc[t][m] = 0ull;

        gemm_core(xs, wsm, acc, cg, rg);

        float* dst = (s == 0) ? qs : ((s == 1) ? ks : vs);
        #pragma unroll
        for (int t = 0; t < 7; ++t) {
            int r = rg + 8 * t;
            if (r < NTOK) {
                #pragma unroll
                for (int m = 0; m < 4; ++m) {
                    int c = cg + 32 * m;
                    float2 p = unpk(acc[t][m]);
                    float v = p.x + p.y + qkv_b[s * 128 + c];
                    if (s == 0) v *= SCALE;
                    dst[r * ROWW + c] = v;
                }
            }
        }
    }
    __syncthreads();

    // ---------- phase 2a: zero attn buffer (pads must be 0) ----------
    for (int idx = tid; idx < 4 * AHS; idx += 256) attn[idx] = 0.f;
    __syncthreads();

    // ---------- phase 2b: QK^T + bias + mask ----------
    {
        const float* maskg = attn_mask + (size_t)(w & 63) * (NTOK * NTOK);
        for (int u = tid; u < 1300; u += 256) {            // 4h * 25ip * 13jq
            int h   = u / 325;
            int rem = u - h * 325;
            int ip  = rem / 13;
            int jq  = rem - ip * 13;
            int i0 = 2 * ip, j0 = 4 * jq;
            const float* qb = qs + i0 * ROWW + h * 32;
            const float* kb = ks + j0 * ROWW + h * 32;
            ull acc[2][4];
            #pragma unroll
            for (int a = 0; a < 2; ++a)
                #pragma unroll
                for (int b = 0; b < 4; ++b) acc[a][b] = 0ull;
            #pragma unroll
            for (int dq = 0; dq < 8; ++dq) {
                int d = 4 * dq;
                ulonglong2 q0 = *(const ulonglong2*)(qb + d);
                ulonglong2 q1 = *(const ulonglong2*)(qb + ROWW + d);
                #pragma unroll
                for (int jj = 0; jj < 4; ++jj) {
                    ulonglong2 kv = *(const ulonglong2*)(kb + jj * ROWW + d);
                    fma2(acc[0][jj], q0.x, kv.x);
                    fma2(acc[0][jj], q0.y, kv.y);
                    fma2(acc[1][jj], q1.x, kv.x);
                    fma2(acc[1][jj], q1.y, kv.y);
                }
            }
            #pragma unroll
            for (int ii = 0; ii < 2; ++ii) {
                int i = i0 + ii;
                if (i < NTOK) {
                    #pragma unroll
                    for (int jj = 0; jj < 4; ++jj) {
                        int j = j0 + jj;
                        if (j < NTOK) {
                            float2 p = unpk(acc[ii][jj]);
                            int ij = i * NTOK + j;
                            float v = p.x + p.y
                                    + bias_table[rel_idx[ij] * 4 + h]
                                    + maskg[ij];
                            attn[h * AHS + i * APAD + j] = v;
                        }
                    }
                }
            }
        }
    }
    __syncthreads();

    // ---------- phase 3: softmax (one warp per row) ----------
    {
        const int warp = tid >> 5, lane = tid & 31;
        for (int row = warp; row < 4 * NTOK; row += 8) {
            int h = row / NTOK, i = row - h * NTOK;
            float* ar = attn + h * AHS + i * APAD;
            float v0 = ar[lane];
            float v1 = (lane + 32 < NTOK) ? ar[lane + 32] : -INFINITY;
            float m = fmaxf(v0, v1);
            #pragma unroll
            for (int o = 16; o; o >>= 1) m = fmaxf(m, __shfl_xor_sync(0xffffffffu, m, o));
            float e0 = __expf(v0 - m);
            float e1 = (lane + 32 < NTOK) ? __expf(v1 - m) : 0.f;
            float ssum = e0 + e1;
            #pragma unroll
            for (int o = 16; o; o >>= 1) ssum += __shfl_xor_sync(0xffffffffu, ssum, o);
            float inv = 1.f / ssum;
            ar[lane] = e0 * inv;
            if (lane + 32 < NTOK) ar[lane + 32] = e1 * inv;
        }
    }
    __syncthreads();

    // ---------- phase 4: attn @ v -> ov ----------
    {
        for (int u = tid; u < 400; u += 256) {             // 25ip * 16co
            int ip = u >> 4, co = u & 15;
            int i0 = 2 * ip, c0 = 8 * co, h = co >> 2;
            const float* ab = attn + h * AHS + i0 * APAD;  // rows i0, i0+1 (row 49 zeroed)
            ull acc[2][4];
            #pragma unroll
            for (int a = 0; a < 2; ++a)
                #pragma unroll
                for (int b = 0; b < 4; ++b) acc[a][b] = 0ull;
            #pragma unroll 7
            for (int j = 0; j < NTOK; ++j) {
                ull a0 = dup2(ab[j]);
                ull a1 = dup2(ab[APAD + j]);
                ulonglong2 vA = *(const ulonglong2*)(vs + j * ROWW + c0);
                ulonglong2 vB = *(const ulonglong2*)(vs + j * ROWW + c0 + 4);
                fma2(acc[0][0], a0, vA.x);  fma2(acc[0][1], a0, vA.y);
                fma2(acc[0][2], a0, vB.x);  fma2(acc[0][3], a0, vB.y);
                fma2(acc[1][0], a1, vA.x);  fma2(acc[1][1], a1, vA.y);
                fma2(acc[1][2], a1, vB.x);  fma2(acc[1][3], a1, vB.y);
            }
            #pragma unroll
            for (int ii = 0; ii < 2; ++ii) {
                int i = i0 + ii;
                if (i < NTOK) {
                    #pragma unroll
                    for (int cc = 0; cc < 4; ++cc)
                        *(float2*)(ov + i * ROWW + c0 + 2 * cc) = unpk(acc[ii][cc]);
                }
            }
        }
    }
    __syncthreads();

    // ---------- phase 5: proj GEMM ----------
    {
        for (int q4 = tid; q4 < 128 * 32; q4 += 256) {     // stage proj_w
            int c = q4 >> 5, k4 = q4 & 31;
            *(float4*)(wsm + c * ROWW + 4 * k4) = *(const float4*)(proj_w + c * DIMC + 4 * k4);
        }
        __syncthreads();

        ull acc[7][4];
        #pragma unroll
        for (int t = 0; t < 7; ++t)
            #pragma unroll
            for (int m = 0; m < 4; ++m) acc[t][m] = 0ull;

        gemm_core(ov, wsm, acc, cg, rg);

        float* og = out + (size_t)w * (NTOK * DIMC);
        #pragma unroll
        for (int t = 0; t < 7; ++t) {
            int r = rg + 8 * t;
            if (r < NTOK) {
                #pragma unroll
                for (int m = 0; m < 4; ++m) {
                    int c = cg + 32 * m;
                    float2 p = unpk(acc[t][m]);
                    og[r * DIMC + c] = p.x + p.y + proj_b[c];
                }
            }
        }
    }
}

extern "C" void kernel_launch(void* const* d_in, const int* in_sizes, int n_in,
                              void* d_out, int out_size)
{
    const float* x          = (const float*)d_in[0];
    const float* attn_mask  = (const float*)d_in[1];
    const float* qkv_w      = (const float*)d_in[2];
    const float* qkv_b      = (const float*)d_in[3];
    const float* proj_w     = (const float*)d_in[4];
    const float* proj_b     = (const float*)d_in[5];
    const float* bias_table = (const float*)d_in[6];
    const int*   rel_idx    = (const int*)d_in[7];
    float* out = (float*)d_out;

    const int smem_bytes = SMEM_FLOATS * sizeof(float);   // 175296 B
    cudaFuncSetAttribute(wmsa_fused_kernel,
                         cudaFuncAttributeMaxDynamicSharedMemorySize, smem_bytes);

    const int n_windows = in_sizes[0] / (NTOK * DIMC);    // 4096
    wmsa_fused_kernel<<<n_windows, 256, smem_bytes>>>(
        x, attn_mask, qkv_w, qkv_b, proj_w, proj_b, bias_table, rel_idx, out);
}

// round 3
// speedup vs baseline: 1.5235x; 1.0846x over previous
#include <cuda_runtime.h>

typedef unsigned long long ull;

#define NTOK   49
#define DIMC   128
#define ROWW   132          // padded row stride (floats), multiple of 4
#define APAD   52           // attn row stride
#define AHS    2600         // attn head stride = 50*52
#define SCALE  0.17677669529663687f
#define NTHR   512

// SMEM float offsets
#define OFF_WS   7392                      // xs: 56*132
#define OFF_QS   24288                     // ws: 128*132
#define OFF_KS   30756                     // qs: 49*132
#define OFF_VS   37224
#define OFF_ATTN 43824                     // vs: 50*132
#define SMEM_FLOATS 54224                  // + attn 4*2600 -> 216896 bytes
// overlay: ov -> xs region (rows 49..55 stay zero for proj GEMM padding)

__device__ __forceinline__ void fma2(ull& d, ull a, ull b) {
    asm("fma.rn.f32x2 %0, %1, %2, %0;" : "+l"(d) : "l"(a), "l"(b));
}
__device__ __forceinline__ ull dup2(float x) {
    ull r; asm("mov.b64 %0, {%1, %1};" : "=l"(r) : "f"(x)); return r;
}
__device__ __forceinline__ float2 unpk(ull v) {
    float2 r; asm("mov.b64 {%0, %1}, %2;" : "=f"(r.x), "=f"(r.y) : "l"(v)); return r;
}

// GEMM core: warp = (row-group rg, col-half ch). Thread tile: rows rg+8t (t<7),
// cols ch*64 + lane + 32m (m<2). K=128 paired via f32x2.
__device__ __forceinline__ void gemm_core(const float* __restrict__ src,
                                          const float* __restrict__ wsm,
                                          ull acc[7][2], int rg, int cbase)
{
    #pragma unroll 2
    for (int kq = 0; kq < 32; ++kq) {
        const int k = kq * 4;
        ulonglong2 xv[7];
        #pragma unroll
        for (int t = 0; t < 7; ++t)
            xv[t] = *(const ulonglong2*)(src + (rg + 8 * t) * ROWW + k);
        #pragma unroll
        for (int m = 0; m < 2; ++m) {
            ulonglong2 wv = *(const ulonglong2*)(wsm + (cbase + 32 * m) * ROWW + k);
            #pragma unroll
            for (int t = 0; t < 7; ++t) {
                fma2(acc[t][m], xv[t].x, wv.x);
                fma2(acc[t][m], xv[t].y, wv.y);
            }
        }
    }
}

__global__ __launch_bounds__(NTHR, 1)
void wmsa_fused_kernel(const float* __restrict__ x,
                       const float* __restrict__ attn_mask,
                       const float* __restrict__ qkv_w,
                       const float* __restrict__ qkv_b,
                       const float* __restrict__ proj_w,
                       const float* __restrict__ proj_b,
                       const float* __restrict__ bias_table,
                       const int*   __restrict__ rel_idx,
                       float* __restrict__ out)
{
    extern __shared__ float sm[];
    const int tid = threadIdx.x;
    const int w   = blockIdx.x;

    float* xs   = sm;                 // 56 x 132 (rows 49..55 zero)
    float* wsm  = sm + OFF_WS;        // 128 x 132
    float* qs   = sm + OFF_QS;
    float* ks   = sm + OFF_KS;
    float* vs   = sm + OFF_VS;
    float* attn = sm + OFF_ATTN;      // 4 x 50 x 52
    float* ov   = sm;                 // overlay over xs

    const int lane = tid & 31;
    const int wid  = tid >> 5;        // 0..15
    const int rg   = wid >> 1;        // row group: rows rg + 8t
    const int cbase = (wid & 1) * 64 + lane;  // cols cbase + 32m, m<2

    // ---------- phase 0: load x (49x128), zero pad rows ----------
    {
        const float* xg = x + (size_t)w * (NTOK * DIMC);
        for (int q4 = tid; q4 < NTOK * 32; q4 += NTHR) {
            int i = q4 >> 5, c4 = q4 & 31;
            *(float4*)(xs + i * ROWW + 4 * c4) = *(const float4*)(xg + i * DIMC + 4 * c4);
        }
        for (int idx = tid; idx < 7 * ROWW; idx += NTHR)
            xs[49 * ROWW + idx] = 0.f;
        // zero attn buffer (pads must read as 0 in AV)
        for (int idx = tid; idx < 4 * AHS; idx += NTHR)
            attn[idx] = 0.f;
    }

    // ---------- phase 1: QKV GEMM, 3 stages of 128 cols ----------
    for (int s = 0; s < 3; ++s) {
        __syncthreads();
        const float* wg = qkv_w + (size_t)s * 128 * DIMC;
        for (int q4 = tid; q4 < 128 * 32; q4 += NTHR) {
            int c = q4 >> 5, k4 = q4 & 31;
            *(float4*)(wsm + c * ROWW + 4 * k4) = *(const float4*)(wg + c * DIMC + 4 * k4);
        }
        __syncthreads();

        ull acc[7][2];
        #pragma unroll
        for (int t = 0; t < 7; ++t) { acc[t][0] = 0ull; acc[t][1] = 0ull; }

        gemm_core(xs, wsm, acc, rg, cbase);

        float* dst = (s == 0) ? qs : ((s == 1) ? ks : vs);
        #pragma unroll
        for (int t = 0; t < 7; ++t) {
            int r = rg + 8 * t;
            if (r < NTOK) {
                #pragma unroll
                for (int m = 0; m < 2; ++m) {
                    int c = cbase + 32 * m;
                    float2 p = unpk(acc[t][m]);
                    float v = p.x + p.y + qkv_b[s * 128 + c];
                    if (s == 0) v *= SCALE;
                    dst[r * ROWW + c] = v;
                }
            }
        }
    }
    __syncthreads();

    // ---------- phase 2: QK^T + bias + mask ----------
    {
        const float* maskg = attn_mask + (size_t)(w & 63) * (NTOK * NTOK);
        for (int u = tid; u < 1300; u += NTHR) {           // 4h * 25ip * 13jq
            int h   = u / 325;
            int rem = u - h * 325;
            int ip  = rem / 13;
            int jq  = rem - ip * 13;
            int i0 = 2 * ip, j0 = 4 * jq;
            const float* qb = qs + i0 * ROWW + h * 32;
            const float* kb = ks + j0 * ROWW + h * 32;
            ull acc[2][4];
            #pragma unroll
            for (int a = 0; a < 2; ++a)
                #pragma unroll
                for (int b = 0; b < 4; ++b) acc[a][b] = 0ull;
            #pragma unroll
            for (int dq = 0; dq < 8; ++dq) {
                int d = 4 * dq;
                ulonglong2 q0 = *(const ulonglong2*)(qb + d);
                ulonglong2 q1 = *(const ulonglong2*)(qb + ROWW + d);
                #pragma unroll
                for (int jj = 0; jj < 4; ++jj) {
                    ulonglong2 kv = *(const ulonglong2*)(kb + jj * ROWW + d);
                    fma2(acc[0][jj], q0.x, kv.x);
                    fma2(acc[0][jj], q0.y, kv.y);
                    fma2(acc[1][jj], q1.x, kv.x);
                    fma2(acc[1][jj], q1.y, kv.y);
                }
            }
            #pragma unroll
            for (int ii = 0; ii < 2; ++ii) {
                int i = i0 + ii;
                if (i < NTOK) {
                    #pragma unroll
                    for (int jj = 0; jj < 4; ++jj) {
                        int j = j0 + jj;
                        if (j < NTOK) {
                            float2 p = unpk(acc[ii][jj]);
                            int ij = i * NTOK + j;
                            attn[h * AHS + i * APAD + j] =
                                p.x + p.y + bias_table[rel_idx[ij] * 4 + h] + maskg[ij];
                        }
                    }
                }
            }
        }
    }
    __syncthreads();

    // ---------- phase 3: softmax (one warp per row) ----------
    {
        for (int row = wid; row < 4 * NTOK; row += 16) {
            int h = row / NTOK, i = row - h * NTOK;
            float* ar = attn + h * AHS + i * APAD;
            float v0 = ar[lane];
            float v1 = (lane + 32 < NTOK) ? ar[lane + 32] : -INFINITY;
            float m = fmaxf(v0, v1);
            #pragma unroll
            for (int o = 16; o; o >>= 1) m = fmaxf(m, __shfl_xor_sync(0xffffffffu, m, o));
            float e0 = __expf(v0 - m);
            float e1 = (lane + 32 < NTOK) ? __expf(v1 - m) : 0.f;
            float ssum = e0 + e1;
            #pragma unroll
            for (int o = 16; o; o >>= 1) ssum += __shfl_xor_sync(0xffffffffu, ssum, o);
            float inv = 1.f / ssum;
            ar[lane] = e0 * inv;
            if (lane + 32 < NTOK) ar[lane + 32] = e1 * inv;
        }
    }
    __syncthreads();

    // ---------- phase 4: attn @ v -> ov (overlay on xs) ----------
    {
        if (tid < 400) {                                  // 25ip * 16co
            int u = tid;
            int ip = u >> 4, co = u & 15;
            int i0 = 2 * ip, c0 = 8 * co, h = co >> 2;
            const float* ab = attn + h * AHS + i0 * APAD;
            ull acc[2][4];
            #pragma unroll
            for (int a = 0; a < 2; ++a)
                #pragma unroll
                for (int b = 0; b < 4; ++b) acc[a][b] = 0ull;
            #pragma unroll 7
            for (int j = 0; j < NTOK; ++j) {
                ull a0 = dup2(ab[j]);
                ull a1 = dup2(ab[APAD + j]);
                ulonglong2 vA = *(const ulonglong2*)(vs + j * ROWW + c0);
                ulonglong2 vB = *(const ulonglong2*)(vs + j * ROWW + c0 + 4);
                fma2(acc[0][0], a0, vA.x);  fma2(acc[0][1], a0, vA.y);
                fma2(acc[0][2], a0, vB.x);  fma2(acc[0][3], a0, vB.y);
                fma2(acc[1][0], a1, vA.x);  fma2(acc[1][1], a1, vA.y);
                fma2(acc[1][2], a1, vB.x);  fma2(acc[1][3], a1, vB.y);
            }
            #pragma unroll
            for (int ii = 0; ii < 2; ++ii) {
                int i = i0 + ii;
                if (i < NTOK) {
                    #pragma unroll
                    for (int cc = 0; cc < 4; ++cc)
                        *(float2*)(ov + i * ROWW + c0 + 2 * cc) = unpk(acc[ii][cc]);
                }
            }
        }
    }
    __syncthreads();

    // ---------- phase 5: proj GEMM ----------
    {
        for (int q4 = tid; q4 < 128 * 32; q4 += NTHR) {
            int c = q4 >> 5, k4 = q4 & 31;
            *(float4*)(wsm + c * ROWW + 4 * k4) = *(const float4*)(proj_w + c * DIMC + 4 * k4);
        }
        __syncthreads();

        ull acc[7][2];
        #pragma unroll
        for (int t = 0; t < 7; ++t) { acc[t][0] = 0ull; acc[t][1] = 0ull; }

        gemm_core(ov, wsm, acc, rg, cbase);

        float* og = out + (size_t)w * (NTOK * DIMC);
        #pragma unroll
        for (int t = 0; t < 7; ++t) {
            int r = rg + 8 * t;
            if (r < NTOK) {
                #pragma unroll
                for (int m = 0; m < 2; ++m) {
                    int c = cbase + 32 * m;
                    float2 p = unpk(acc[t][m]);
                    og[r * DIMC + c] = p.x + p.y + proj_b[c];
                }
            }
        }
    }
}

extern "C" void kernel_launch(void* const* d_in, const int* in_sizes, int n_in,
                              void* d_out, int out_size)
{
    const float* x          = (const float*)d_in[0];
    const float* attn_mask  = (const float*)d_in[1];
    const float* qkv_w      = (const float*)d_in[2];
    const float* qkv_b      = (const float*)d_in[3];
    const float* proj_w     = (const float*)d_in[4];
    const float* proj_b     = (const float*)d_in[5];
    const float* bias_table = (const float*)d_in[6];
    const int*   rel_idx    = (const int*)d_in[7];
    float* out = (float*)d_out;

    const int smem_bytes = SMEM_FLOATS * sizeof(float);   // 216896 B
    cudaFuncSetAttribute(wmsa_fused_kernel,
                         cudaFuncAttributeMaxDynamicSharedMemorySize, smem_bytes);

    const int n_windows = in_sizes[0] / (NTOK * DIMC);    // 4096
    wmsa_fused_kernel<<<n_windows, NTHR, smem_bytes>>>(
        x, attn_mask, qkv_w, qkv_b, proj_w, proj_b, bias_table, rel_idx, out);
}

// round 4
// speedup vs baseline: 1.9005x; 1.2475x over previous
#include <cuda_runtime.h>

#define NTOK   49
#define DIMC   128
#define ROWW   132          // row stride (floats) for x/w/q/k/v tiles: (4g+t) bank-clean
#define APAD   56           // attn row stride
#define AHS    2800         // attn head stride = 50*56
#define SCALE  0.17677669529663687f
#define NTHR   512

// SMEM float offsets
#define OFF_WS   8448                      // xs: 64*132
#define OFF_QS   25344                     // ws: 128*132
#define OFF_KS   31812                     // qs: 49*132
#define OFF_VS   39204                     // ks: 56*132
#define OFF_ATTN 46596                     // vs: 56*132
#define SMEM_FLOATS 57796                  // + attn 4*2800 -> 231184 bytes
// overlay: ov -> xs region (rows 49..63 stay zero for proj GEMM padding)

__device__ __forceinline__ unsigned f2tf(float x) {
    unsigned r; asm("cvt.rna.tf32.f32 %0, %1;" : "=r"(r) : "f"(x)); return r;
}
__device__ __forceinline__ void split2(float x, unsigned& hi, unsigned& lo) {
    hi = f2tf(x);
    lo = f2tf(x - __uint_as_float(hi));
}
__device__ __forceinline__ void mma8(float* d, const unsigned* a, const unsigned* b) {
    asm volatile("mma.sync.aligned.m16n8k8.row.col.f32.tf32.tf32.f32 "
        "{%0,%1,%2,%3},{%4,%5,%6,%7},{%8,%9},{%0,%1,%2,%3};"
        : "+f"(d[0]), "+f"(d[1]), "+f"(d[2]), "+f"(d[3])
        : "r"(a[0]), "r"(a[1]), "r"(a[2]), "r"(a[3]), "r"(b[0]), "r"(b[1]));
}
// split + 3-pass mma (hi*lo + lo*hi + hi*hi): fp32-class accuracy
__device__ __forceinline__ void mma3(float* d, const unsigned* ah, const unsigned* al,
                                     float b0f, float b1f) {
    unsigned bh[2], bl[2];
    split2(b0f, bh[0], bl[0]);
    split2(b1f, bh[1], bl[1]);
    mma8(d, ah, bl);
    mma8(d, al, bh);
    mma8(d, ah, bh);
}

// Dense stage: D(16x32 per warp) = A(rows rb..rb+15, K=128) * W^T(cols cb..cb+31)
// A stride ROWW (rows 0..63 readable), W layout [c][k] stride ROWW.
__device__ __forceinline__ void mma_dense(const float* __restrict__ A,
                                          const float* __restrict__ W,
                                          float d[4][4], int rb, int cb, int g, int t)
{
    #pragma unroll 4
    for (int kb = 0; kb < 16; ++kb) {
        const int k = kb * 8;
        const float* ap = A + (rb + g) * ROWW + k + t;
        float a0 = ap[0];
        float a1 = ap[8 * ROWW];
        float a2 = ap[4];
        float a3 = ap[8 * ROWW + 4];
        unsigned ah[4], al[4];
        split2(a0, ah[0], al[0]);
        split2(a1, ah[1], al[1]);
        split2(a2, ah[2], al[2]);
        split2(a3, ah[3], al[3]);
        #pragma unroll
        for (int j = 0; j < 4; ++j) {
            const float* wp = W + (cb + j * 8 + g) * ROWW + k + t;
            mma3(d[j], ah, al, wp[0], wp[4]);
        }
    }
}

__global__ __launch_bounds__(NTHR, 1)
void wmsa_fused_kernel(const float* __restrict__ x,
                       const float* __restrict__ attn_mask,
                       const float* __restrict__ qkv_w,
                       const float* __restrict__ qkv_b,
                       const float* __restrict__ proj_w,
                       const float* __restrict__ proj_b,
                       const float* __restrict__ bias_table,
                       const int*   __restrict__ rel_idx,
                       float* __restrict__ out)
{
    extern __shared__ float sm[];
    const int tid = threadIdx.x;
    const int w   = blockIdx.x;

    float* xs   = sm;                 // 64 x 132 (rows 49..63 zero)
    float* wsm  = sm + OFF_WS;        // 128 x 132
    float* qs   = sm + OFF_QS;        // 49 x 132
    float* ks   = sm + OFF_KS;        // 56 x 132 (rows 49..55 zero)
    float* vs   = sm + OFF_VS;        // 56 x 132 (rows 49..55 zero)
    float* attn = sm + OFF_ATTN;      // 4 x 50 x 56
    float* ov   = sm;                 // overlay over xs

    const int lane = tid & 31;
    const int wid  = tid >> 5;        // 0..15
    const int g    = lane >> 2;       // mma group id 0..7
    const int t    = lane & 3;        // thread-in-group 0..3
    const int mt   = wid >> 2;        // m-tile 0..3  (rows mt*16 ..)
    const int nq   = wid & 3;         // n-quarter 0..3

    const float* maskg = attn_mask + (size_t)(w & 63) * (NTOK * NTOK);

    // ---------- phase 0: load x, zero pads, materialize bias+mask into attn ----------
    {
        const float* xg = x + (size_t)w * (NTOK * DIMC);
        for (int q4 = tid; q4 < NTOK * 32; q4 += NTHR) {
            int i = q4 >> 5, c4 = q4 & 31;
            *(float4*)(xs + i * ROWW + 4 * c4) = *(const float4*)(xg + i * DIMC + 4 * c4);
        }
        for (int idx = tid; idx < 15 * ROWW; idx += NTHR)      // xs rows 49..63
            xs[49 * ROWW + idx] = 0.f;
        for (int idx = tid; idx < 7 * ROWW; idx += NTHR) {     // ks/vs rows 49..55
            ks[49 * ROWW + idx] = 0.f;
            vs[49 * ROWW + idx] = 0.f;
        }
        for (int u = tid; u < 4 * AHS; u += NTHR) {            // attn = bias + mask (pad=0)
            int h = u / AHS, rem = u - h * AHS;
            int i = rem / APAD, j = rem - i * APAD;
            float v = 0.f;
            if (i < NTOK && j < NTOK) {
                int ij = i * NTOK + j;
                v = bias_table[rel_idx[ij] * 4 + h] + maskg[ij];
            }
            attn[u] = v;
        }
    }

    // ---------- phase 1: QKV GEMM via tf32 mma, 3 stages ----------
    const int rb = mt * 16, cb = nq * 32;
    for (int s = 0; s < 3; ++s) {
        __syncthreads();
        const float* wg = qkv_w + (size_t)s * 128 * DIMC;
        for (int q4 = tid; q4 < 128 * 32; q4 += NTHR) {
            int c = q4 >> 5, k4 = q4 & 31;
            *(float4*)(wsm + c * ROWW + 4 * k4) = *(const float4*)(wg + c * DIMC + 4 * k4);
        }
        __syncthreads();

        float d[4][4] = {};
        mma_dense(xs, wsm, d, rb, cb, g, t);

        float* dst = (s == 0) ? qs : ((s == 1) ? ks : vs);
        const int r0 = rb + g, r1 = rb + g + 8;
        #pragma unroll
        for (int j = 0; j < 4; ++j) {
            int c = cb + j * 8 + 2 * t;
            float b0 = qkv_b[s * 128 + c], b1 = qkv_b[s * 128 + c + 1];
            if (r0 < NTOK) {
                float v0 = d[j][0] + b0, v1 = d[j][1] + b1;
                if (s == 0) { v0 *= SCALE; v1 *= SCALE; }
                dst[r0 * ROWW + c] = v0; dst[r0 * ROWW + c + 1] = v1;
            }
            if (r1 < NTOK) {
                float v2 = d[j][2] + b0, v3 = d[j][3] + b1;
                if (s == 0) { v2 *= SCALE; v3 *= SCALE; }
                dst[r1 * ROWW + c] = v2; dst[r1 * ROWW + c + 1] = v3;
            }
        }
    }
    __syncthreads();

    // ---------- phase 2: stage proj_w (hides LDG) + QK^T via mma ----------
    {
        for (int q4 = tid; q4 < 128 * 32; q4 += NTHR) {
            int c = q4 >> 5, k4 = q4 & 31;
            *(float4*)(wsm + c * ROWW + 4 * k4) = *(const float4*)(proj_w + c * DIMC + 4 * k4);
        }

        const int h = wid >> 2, qt = wid & 3;     // warp = (head, m-tile)
        const int qrb = qt * 16;
        const float* Aq = qs + h * 32;
        const float* Bk = ks + h * 32;
        float* at = attn + h * AHS;
        const int r0c = min(qrb + g, 49);         // attn init (row 49 = zeros)
        const int r1c = min(qrb + g + 8, 49);
        const int ra  = min(qrb + g, 48);         // q row clamp (discarded rows)
        const int ra8 = min(qrb + g + 8, 48);

        float d[7][4];
        #pragma unroll
        for (int j = 0; j < 7; ++j) {
            int c = j * 8 + 2 * t;
            d[j][0] = at[r0c * APAD + c];   d[j][1] = at[r0c * APAD + c + 1];
            d[j][2] = at[r1c * APAD + c];   d[j][3] = at[r1c * APAD + c + 1];
        }
        #pragma unroll
        for (int kb = 0; kb < 4; ++kb) {
            const int k = kb * 8;
            float a0 = Aq[ra  * ROWW + k + t];
            float a1 = Aq[ra8 * ROWW + k + t];
            float a2 = Aq[ra  * ROWW + k + t + 4];
            float a3 = Aq[ra8 * ROWW + k + t + 4];
            unsigned ah[4], al[4];
            split2(a0, ah[0], al[0]);  split2(a1, ah[1], al[1]);
            split2(a2, ah[2], al[2]);  split2(a3, ah[3], al[3]);
            #pragma unroll
            for (int j = 0; j < 7; ++j) {
                const float* kp = Bk + (j * 8 + g) * ROWW + k + t;
                mma3(d[j], ah, al, kp[0], kp[4]);
            }
        }
        const int r0 = qrb + g, r1 = qrb + g + 8;
        #pragma unroll
        for (int j = 0; j < 7; ++j) {
            int c = j * 8 + 2 * t;
            if (r0 < NTOK) {
                if (c < NTOK)     at[r0 * APAD + c]     = d[j][0];
                if (c + 1 < NTOK) at[r0 * APAD + c + 1] = d[j][1];
            }
            if (r1 < NTOK) {
                if (c < NTOK)     at[r1 * APAD + c]     = d[j][2];
                if (c + 1 < NTOK) at[r1 * APAD + c + 1] = d[j][3];
            }
        }
    }
    __syncthreads();

    // ---------- phase 3: softmax (one warp per row) ----------
    {
        for (int row = wid; row < 4 * NTOK; row += 16) {
            int h = row / NTOK, i = row - h * NTOK;
            float* ar = attn + h * AHS + i * APAD;
            float v0 = ar[lane];
            float v1 = (lane + 32 < NTOK) ? ar[lane + 32] : -INFINITY;
            float m = fmaxf(v0, v1);
            #pragma unroll
            for (int o = 16; o; o >>= 1) m = fmaxf(m, __shfl_xor_sync(0xffffffffu, m, o));
            float e0 = __expf(v0 - m);
            float e1 = (lane + 32 < NTOK) ? __expf(v1 - m) : 0.f;
            float ssum = e0 + e1;
            #pragma unroll
            for (int o = 16; o; o >>= 1) ssum += __shfl_xor_sync(0xffffffffu, ssum, o);
            float inv = 1.f / ssum;
            ar[lane] = e0 * inv;
            if (lane + 32 < NTOK) ar[lane + 32] = e1 * inv;
        }
    }
    __syncthreads();

    // ---------- phase 4: AV via mma -> ov (overlay on xs) ----------
    {
        const int h = wid >> 2, qt = wid & 3;
        const int qrb = qt * 16;
        const float* at = attn + h * AHS;
        const float* Bv = vs + h * 32;
        const int ra  = min(qrb + g, 48);
        const int ra8 = min(qrb + g + 8, 48);

        float d[4][4] = {};
        #pragma unroll
        for (int kb = 0; kb < 7; ++kb) {
            const int k = kb * 8;
            float a0 = at[ra  * APAD + k + t];
            float a1 = at[ra8 * APAD + k + t];
            float a2 = at[ra  * APAD + k + t + 4];
            float a3 = at[ra8 * APAD + k + t + 4];
            unsigned ah[4], al[4];
            split2(a0, ah[0], al[0]);  split2(a1, ah[1], al[1]);
            split2(a2, ah[2], al[2]);  split2(a3, ah[3], al[3]);
            #pragma unroll
            for (int j = 0; j < 4; ++j) {
                float b0 = Bv[(k + t) * ROWW + j * 8 + g];
                float b1 = Bv[(k + t + 4) * ROWW + j * 8 + g];
                mma3(d[j], ah, al, b0, b1);
            }
        }
        const int r0 = qrb + g, r1 = qrb + g + 8;
        #pragma unroll
        for (int j = 0; j < 4; ++j) {
            int c = h * 32 + j * 8 + 2 * t;
            if (r0 < NTOK) { ov[r0 * ROWW + c] = d[j][0]; ov[r0 * ROWW + c + 1] = d[j][1]; }
            if (r1 < NTOK) { ov[r1 * ROWW + c] = d[j][2]; ov[r1 * ROWW + c + 1] = d[j][3]; }
        }
    }
    __syncthreads();

    // ---------- phase 5: proj GEMM via mma (wsm holds proj_w) ----------
    {
        float d[4][4] = {};
        mma_dense(ov, wsm, d, rb, cb, g, t);

        float* og = out + (size_t)w * (NTOK * DIMC);
        const int r0 = rb + g, r1 = rb + g + 8;
        #pragma unroll
        for (int j = 0; j < 4; ++j) {
            int c = cb + j * 8 + 2 * t;
            float b0 = proj_b[c], b1 = proj_b[c + 1];
            if (r0 < NTOK) {
                og[r0 * DIMC + c]     = d[j][0] + b0;
                og[r0 * DIMC + c + 1] = d[j][1] + b1;
            }
            if (r1 < NTOK) {
                og[r1 * DIMC + c]     = d[j][2] + b0;
                og[r1 * DIMC + c + 1] = d[j][3] + b1;
            }
        }
    }
}

extern "C" void kernel_launch(void* const* d_in, const int* in_sizes, int n_in,
                              void* d_out, int out_size)
{
    const float* x          = (const float*)d_in[0];
    const float* attn_mask  = (const float*)d_in[1];
    const float* qkv_w      = (const float*)d_in[2];
    const float* qkv_b      = (const float*)d_in[3];
    const float* proj_w     = (const float*)d_in[4];
    const float* proj_b     = (const float*)d_in[5];
    const float* bias_table = (const float*)d_in[6];
    const int*   rel_idx    = (const int*)d_in[7];
    float* out = (float*)d_out;

    const int smem_bytes = SMEM_FLOATS * sizeof(float);   // 231184 B
    cudaFuncSetAttribute(wmsa_fused_kernel,
                         cudaFuncAttributeMaxDynamicSharedMemorySize, smem_bytes);

    const int n_windows = in_sizes[0] / (NTOK * DIMC);    // 4096
    wmsa_fused_kernel<<<n_windows, NTHR, smem_bytes>>>(
        x, attn_mask, qkv_w, qkv_b, proj_w, proj_b, bias_table, rel_idx, out);
}

// round 5
// speedup vs baseline: 2.6863x; 1.4134x over previous
#include <cuda_runtime.h>

#define NTOK  49
#define SCALE 0.17677669529663687f
#define NTHR  512

// smem offsets in uint2 (8-byte) units
#define O_XH 0            // x / ov tile: 49 x 68
#define O_WH 3332         // weight chunk: 64 x 68
#define O_QH 7684         // q: 49 x 68
#define O_KH 11016        // k: 56 x 68 (rows 49..55 garbage, n-dim only)
#define O_VT 14824        // vT: 128 x 36 (k-packed along tokens)
#define O_SC 19432        // scores fp32 / packed attn: 4 x 56 x 36 (also v fp32 temp)
#define SM_U2 27496       // 219,968 bytes

// pre-split weights: [8 chunks of 64 cols][64 k-words], uint2 = (hi bf16x2, lo bf16x2)
__device__ uint2 gW[8 * 64 * 64];

__device__ __forceinline__ unsigned pack_bf(float x0, float x1) {
    unsigned r;
    asm("cvt.rn.bf16x2.f32 %0, %1, %2;" : "=r"(r) : "f"(x1), "f"(x0));
    return r;  // low half = bf16(x0), high half = bf16(x1)
}
__device__ __forceinline__ uint2 split_pack(float x0, float x1) {
    unsigned h = pack_bf(x0, x1);
    float h0 = __uint_as_float(h << 16);
    float h1 = __uint_as_float(h & 0xffff0000u);
    unsigned l = pack_bf(x0 - h0, x1 - h1);
    return make_uint2(h, l);
}
__device__ __forceinline__ void mmabf(float* d, const unsigned* a, const unsigned* b) {
    asm volatile("mma.sync.aligned.m16n8k16.row.col.f32.bf16.bf16.f32 "
        "{%0,%1,%2,%3},{%4,%5,%6,%7},{%8,%9},{%0,%1,%2,%3};"
        : "+f"(d[0]), "+f"(d[1]), "+f"(d[2]), "+f"(d[3])
        : "r"(a[0]), "r"(a[1]), "r"(a[2]), "r"(a[3]), "r"(b[0]), "r"(b[1]));
}
// 3-pass split mma: d += (Ah+Al)*(Bh+Bl) sans lo*lo
__device__ __forceinline__ void mma3(float* d, const unsigned ah[4], const unsigned al[4],
                                     uint2 b0, uint2 b1) {
    unsigned bh[2] = {b0.x, b1.x};
    unsigned bl[2] = {b0.y, b1.y};
    mmabf(d, ah, bl);
    mmabf(d, al, bh);
    mmabf(d, ah, bh);
}

// dense GEMM stage: D(16x16 per warp) = A(rows, K=128) * W^T(16 cols), all pre-split
__device__ __forceinline__ void mma_dense(const uint2* __restrict__ A,
                                          const uint2* __restrict__ W,
                                          float d[2][4], int ra, int ra8, int wc, int t)
{
    #pragma unroll
    for (int kb = 0; kb < 8; ++kb) {
        const int kw = kb * 8 + t;
        uint2 a0 = A[ra  * 68 + kw];
        uint2 a1 = A[ra8 * 68 + kw];
        uint2 a2 = A[ra  * 68 + kw + 4];
        uint2 a3 = A[ra8 * 68 + kw + 4];
        unsigned ah[4] = {a0.x, a1.x, a2.x, a3.x};
        unsigned al[4] = {a0.y, a1.y, a2.y, a3.y};
        #pragma unroll
        for (int nb = 0; nb < 2; ++nb) {
            mma3(d[nb], ah, al,
                 W[(wc + nb * 8) * 68 + kw],
                 W[(wc + nb * 8) * 68 + kw + 4]);
        }
    }
}

__global__ void prep_kernel(const float* __restrict__ qkv_w,
                            const float* __restrict__ proj_w)
{
    int idx = blockIdx.x * blockDim.x + threadIdx.x;   // 0..32767
    int c = idx >> 6, u = idx & 63;
    const float* src = (c < 384) ? (qkv_w + (size_t)c * 128)
                                 : (proj_w + (size_t)(c - 384) * 128);
    gW[idx] = split_pack(src[2 * u], src[2 * u + 1]);
}

__global__ __launch_bounds__(NTHR, 1)
void wmsa_fused_kernel(const float* __restrict__ x,
                       const float* __restrict__ attn_mask,
                       const float* __restrict__ qkv_b,
                       const float* __restrict__ proj_b,
                       const float* __restrict__ bias_table,
                       const int*   __restrict__ rel_idx,
                       float* __restrict__ out)
{
    extern __shared__ uint2 smu[];
    uint2* XH = smu + O_XH;
    uint2* WH = smu + O_WH;
    uint2* QH = smu + O_QH;
    uint2* KH = smu + O_KH;
    uint2* VT = smu + O_VT;
    uint2* SC = smu + O_SC;

    const int tid  = threadIdx.x;
    const int w    = blockIdx.x;
    const int lane = tid & 31;
    const int wid  = tid >> 5;
    const int g    = lane >> 2;     // mma group 0..7
    const int t    = lane & 3;      // thread-in-group 0..3
    const int mt   = wid >> 2;      // m-tile 0..3 (rows mt*16..)
    const int nq   = wid & 3;       // n-quarter (16 cols)

    const int rb  = mt * 16;
    const int r0  = rb + g, r1 = rb + g + 8;
    const int ra  = min(r0, 48);    // clamped A rows (overflow rows discarded)
    const int ra8 = min(r1, 48);

    const float* maskg = attn_mask + (size_t)(w & 63) * (NTOK * NTOK);

    // ---------- phase 0: load + split x ----------
    {
        const float* xg = x + (size_t)w * (NTOK * 128);
        for (int idx = tid; idx < NTOK * 64; idx += NTHR) {
            int i = idx >> 6, u = idx & 63;
            float2 v = *(const float2*)(xg + i * 128 + 2 * u);
            XH[i * 68 + u] = split_pack(v.x, v.y);
        }
    }

    // ---------- phase 1: QKV GEMM (6 chunks of 64 cols) ----------
    for (int cc = 0; cc < 6; ++cc) {
        __syncthreads();
        const uint2* gsrc = gW + (size_t)cc * 4096;
        for (int idx = tid; idx < 4096; idx += NTHR) {
            int rr = idx >> 6, u = idx & 63;
            WH[rr * 68 + u] = gsrc[idx];
        }
        __syncthreads();

        float d[2][4] = {};
        mma_dense(XH, WH, d, ra, ra8, nq * 16 + g, t);

        const int sel = cc >> 1;                 // 0=q 1=k 2=v
        uint2* dst = (sel == 0) ? QH : KH;
        #pragma unroll
        for (int nb = 0; nb < 2; ++nb) {
            int lc = nq * 16 + nb * 8 + 2 * t;   // local col (even)
            int gc = cc * 64 + lc;
            float b0 = qkv_b[gc], b1 = qkv_b[gc + 1];
            float v00 = d[nb][0] + b0, v01 = d[nb][1] + b1;
            float v10 = d[nb][2] + b0, v11 = d[nb][3] + b1;
            if (sel == 0) { v00 *= SCALE; v01 *= SCALE; v10 *= SCALE; v11 *= SCALE; }
            int wcol = (cc & 1) * 32 + lc / 2;
            if (sel < 2) {
                if (r0 < NTOK) dst[r0 * 68 + wcol] = split_pack(v00, v01);
                if (r1 < NTOK) dst[r1 * 68 + wcol] = split_pack(v10, v11);
            } else {
                float2* vt = (float2*)SC;        // v fp32 temp, row stride 66 float2
                if (r0 < NTOK) vt[r0 * 66 + wcol] = make_float2(v00, v01);
                if (r1 < NTOK) vt[r1 * 66 + wcol] = make_float2(v10, v11);
            }
        }
    }
    __syncthreads();

    // ---------- phase 1.5: transpose+split v -> VT[c][u] (u = token pair) ----------
    {
        const float* vf = (const float*)SC;      // row stride 132 floats
        for (int s = 0; s < 8; ++s) {
            int tau = wid + 16 * s;              // 0..127
            int uB = tau & 7, cB = tau >> 3;
            int u = uB * 4 + t;
            int c = cB * 8 + g;
            int j0 = 2 * u, j1 = 2 * u + 1;
            float x0 = (j0 < NTOK) ? vf[j0 * 132 + c] : 0.f;
            float x1 = (j1 < NTOK) ? vf[j1 * 132 + c] : 0.f;
            VT[c * 36 + u] = split_pack(x0, x1);
        }
    }
    __syncthreads();

    // ---------- phase 2: QK^T + bias + mask -> SC scores fp32 ----------
    {
        const int h = wid >> 2, qt = wid & 3;
        const int qr0 = qt * 16 + g, qr1 = qr0 + 8;
        const int qa  = min(qr0, 48), qa8 = min(qr1, 48);

        float d[7][4] = {};
        #pragma unroll
        for (int kb = 0; kb < 2; ++kb) {
            const int kw = 16 * h + kb * 8 + t;
            uint2 a0 = QH[qa  * 68 + kw];
            uint2 a1 = QH[qa8 * 68 + kw];
            uint2 a2 = QH[qa  * 68 + kw + 4];
            uint2 a3 = QH[qa8 * 68 + kw + 4];
            unsigned ah[4] = {a0.x, a1.x, a2.x, a3.x};
            unsigned al[4] = {a0.y, a1.y, a2.y, a3.y};
            #pragma unroll
            for (int jb = 0; jb < 7; ++jb) {
                mma3(d[jb], ah, al,
                     KH[(jb * 8 + g) * 68 + kw],
                     KH[(jb * 8 + g) * 68 + kw + 4]);
            }
        }
        float2* scf = (float2*)(SC + (size_t)h * 56 * 36);  // row stride 36 float2
        #pragma unroll
        for (int jb = 0; jb < 7; ++jb) {
            int j0 = jb * 8 + 2 * t, j1 = j0 + 1;
            if (qr0 < NTOK) {
                float s0 = d[jb][0], s1 = d[jb][1];
                if (j0 < NTOK) { int ij = qr0 * NTOK + j0; s0 += bias_table[rel_idx[ij] * 4 + h] + maskg[ij]; }
                if (j1 < NTOK) { int ij = qr0 * NTOK + j1; s1 += bias_table[rel_idx[ij] * 4 + h] + maskg[ij]; }
                scf[qr0 * 36 + jb * 4 + t] = make_float2(s0, s1);
            }
            if (qr1 < NTOK) {
                float s2 = d[jb][2], s3 = d[jb][3];
                if (j0 < NTOK) { int ij = qr1 * NTOK + j0; s2 += bias_table[rel_idx[ij] * 4 + h] + maskg[ij]; }
                if (j1 < NTOK) { int ij = qr1 * NTOK + j1; s3 += bias_table[rel_idx[ij] * 4 + h] + maskg[ij]; }
                scf[qr1 * 36 + jb * 4 + t] = make_float2(s2, s3);
            }
        }
    }
    __syncthreads();

    // ---------- phase 3: softmax, write packed attn in-place (lane owns slot) ----------
    {
        for (int row = wid; row < 4 * NTOK; row += 16) {
            int h = row / NTOK, i = row - h * NTOK;
            uint2* arow = SC + ((size_t)h * 56 + i) * 36;
            float2 val = ((float2*)arow)[lane];
            int j0 = 2 * lane, j1 = j0 + 1;
            float v0 = (j0 < NTOK) ? val.x : -INFINITY;
            float v1 = (j1 < NTOK) ? val.y : -INFINITY;
            float m = fmaxf(v0, v1);
            #pragma unroll
            for (int o = 16; o; o >>= 1) m = fmaxf(m, __shfl_xor_sync(0xffffffffu, m, o));
            float e0 = (j0 < NTOK) ? __expf(v0 - m) : 0.f;
            float e1 = (j1 < NTOK) ? __expf(v1 - m) : 0.f;
            float ssum = e0 + e1;
            #pragma unroll
            for (int o = 16; o; o >>= 1) ssum += __shfl_xor_sync(0xffffffffu, ssum, o);
            float inv = 1.f / ssum;
            arow[lane] = split_pack(e0 * inv, e1 * inv);
        }
    }
    __syncthreads();

    // ---------- phase 4: AV -> ov (packed, overlay on XH) ----------
    {
        const int h = wid >> 2, qt = wid & 3;
        const int qr0 = qt * 16 + g, qr1 = qr0 + 8;
        const int qa  = min(qr0, 48), qa8 = min(qr1, 48);
        const uint2* ab = SC + (size_t)h * 56 * 36;

        float d[4][4] = {};
        #pragma unroll
        for (int kb = 0; kb < 4; ++kb) {
            const int kw = kb * 8 + t;
            uint2 a0 = ab[qa  * 36 + kw];
            uint2 a1 = ab[qa8 * 36 + kw];
            uint2 a2 = ab[qa  * 36 + kw + 4];
            uint2 a3 = ab[qa8 * 36 + kw + 4];
            unsigned ah[4] = {a0.x, a1.x, a2.x, a3.x};
            unsigned al[4] = {a0.y, a1.y, a2.y, a3.y};
            #pragma unroll
            for (int nb = 0; nb < 4; ++nb) {
                int c = 32 * h + nb * 8 + g;
                mma3(d[nb], ah, al, VT[c * 36 + kw], VT[c * 36 + kw + 4]);
            }
        }
        #pragma unroll
        for (int nb = 0; nb < 4; ++nb) {
            int cw = 16 * h + nb * 4 + t;      // uint2 word col
            if (qr0 < NTOK) XH[qr0 * 68 + cw] = split_pack(d[nb][0], d[nb][1]);
            if (qr1 < NTOK) XH[qr1 * 68 + cw] = split_pack(d[nb][2], d[nb][3]);
        }
    }
    __syncthreads();

    // ---------- phase 5: proj GEMM (2 chunks) ----------
    float* og = out + (size_t)w * (NTOK * 128);
    for (int cc = 6; cc < 8; ++cc) {
        if (cc > 6) __syncthreads();
        const uint2* gsrc = gW + (size_t)cc * 4096;
        for (int idx = tid; idx < 4096; idx += NTHR) {
            int rr = idx >> 6, u = idx & 63;
            WH[rr * 68 + u] = gsrc[idx];
        }
        __syncthreads();

        float d[2][4] = {};
        mma_dense(XH, WH, d, ra, ra8, nq * 16 + g, t);

        #pragma unroll
        for (int nb = 0; nb < 2; ++nb) {
            int c = (cc - 6) * 64 + nq * 16 + nb * 8 + 2 * t;
            float b0 = proj_b[c], b1 = proj_b[c + 1];
            if (r0 < NTOK) *(float2*)(og + r0 * 128 + c) = make_float2(d[nb][0] + b0, d[nb][1] + b1);
            if (r1 < NTOK) *(float2*)(og + r1 * 128 + c) = make_float2(d[nb][2] + b0, d[nb][3] + b1);
        }
    }
}

extern "C" void kernel_launch(void* const* d_in, const int* in_sizes, int n_in,
                              void* d_out, int out_size)
{
    const float* x          = (const float*)d_in[0];
    const float* attn_mask  = (const float*)d_in[1];
    const float* qkv_w      = (const float*)d_in[2];
    const float* qkv_b      = (const float*)d_in[3];
    const float* proj_w     = (const float*)d_in[4];
    const float* proj_b     = (const float*)d_in[5];
    const float* bias_table = (const float*)d_in[6];
    const int*   rel_idx    = (const int*)d_in[7];
    float* out = (float*)d_out;

    prep_kernel<<<64, 512>>>(qkv_w, proj_w);

    const int smem_bytes = SM_U2 * sizeof(uint2);   // 219,968 B
    cudaFuncSetAttribute(wmsa_fused_kernel,
                         cudaFuncAttributeMaxDynamicSharedMemorySize, smem_bytes);

    const int n_windows = in_sizes[0] / (NTOK * 128);   // 4096
    wmsa_fused_kernel<<<n_windows, NTHR, smem_bytes>>>(
        x, attn_mask, qkv_b, proj_b, bias_table, rel_idx, out);
}

// round 6
// speedup vs baseline: 3.5330x; 1.3152x over previous
#include <cuda_runtime.h>

#define NTOK  49
#define SCALE 0.17677669529663687f
#define NTHR  512

// u2 (8-byte) offsets
#define O_X   0        // R1: x -> q packed, 112 x 68 = 7616
#define O_W   7616     // R2: weight chunk 64 x 68 (region 4992 incl. attn spill)
#define O_K   12608    // R3: k packed 112 x 68 = 7616 ; later OV
#define O_VT  20224    // R4: vT packed [2][128][34] = 8704
#define SM_U2 28928    // 231,424 bytes
#define VSTR  34
// attn overlay: [0, 12544) over R1+R2 : [(win*4+h)*49+i]*32 + u

__device__ uint2 gW[8 * 64 * 64];   // pre-split weights, 8 chunks of 64 cols

__device__ __forceinline__ unsigned pack_bf(float x0, float x1) {
    unsigned r;
    asm("cvt.rn.bf16x2.f32 %0, %1, %2;" : "=r"(r) : "f"(x1), "f"(x0));
    return r;
}
__device__ __forceinline__ uint2 split_pack(float x0, float x1) {
    unsigned h = pack_bf(x0, x1);
    float h0 = __uint_as_float(h << 16);
    float h1 = __uint_as_float(h & 0xffff0000u);
    unsigned l = pack_bf(x0 - h0, x1 - h1);
    return make_uint2(h, l);
}
__device__ __forceinline__ void mmabf(float* d, const unsigned* a, const unsigned* b) {
    asm volatile("mma.sync.aligned.m16n8k16.row.col.f32.bf16.bf16.f32 "
        "{%0,%1,%2,%3},{%4,%5,%6,%7},{%8,%9},{%0,%1,%2,%3};"
        : "+f"(d[0]), "+f"(d[1]), "+f"(d[2]), "+f"(d[3])
        : "r"(a[0]), "r"(a[1]), "r"(a[2]), "r"(a[3]), "r"(b[0]), "r"(b[1]));
}
__device__ __forceinline__ void mma3(float* d, const unsigned ah[4], const unsigned al[4],
                                     uint2 b0, uint2 b1) {
    unsigned bh[2] = {b0.x, b1.x};
    unsigned bl[2] = {b0.y, b1.y};
    mmabf(d, ah, bl);
    mmabf(d, al, bh);
    mmabf(d, ah, bh);
}

// D(16x32 per warp) = A(rows ra/ra8.., K=128) x W^T(cols wc+8nb), all pre-split
__device__ __forceinline__ void mma_dense(const uint2* __restrict__ A,
                                          const uint2* __restrict__ W,
                                          float d[4][4], int ra, int ra8, int wc, int t)
{
    #pragma unroll
    for (int kb = 0; kb < 8; ++kb) {
        const int kw = kb * 8 + t;
        uint2 a0 = A[ra  * 68 + kw];
        uint2 a1 = A[ra8 * 68 + kw];
        uint2 a2 = A[ra  * 68 + kw + 4];
        uint2 a3 = A[ra8 * 68 + kw + 4];
        unsigned ah[4] = {a0.x, a1.x, a2.x, a3.x};
        unsigned al[4] = {a0.y, a1.y, a2.y, a3.y};
        #pragma unroll
        for (int nb = 0; nb < 4; ++nb)
            mma3(d[nb], ah, al, W[(wc + nb * 8) * 68 + kw],
                                W[(wc + nb * 8) * 68 + kw + 4]);
    }
}

__global__ void prep_kernel(const float* __restrict__ qkv_w,
                            const float* __restrict__ proj_w)
{
    int idx = blockIdx.x * blockDim.x + threadIdx.x;   // 0..32767
    int c = idx >> 6, u = idx & 63;
    const float* src = (c < 384) ? (qkv_w + (size_t)c * 128)
                                 : (proj_w + (size_t)(c - 384) * 128);
    gW[idx] = split_pack(src[2 * u], src[2 * u + 1]);
}

__global__ __launch_bounds__(NTHR, 1)
void wmsa_fused_kernel(const float* __restrict__ x,
                       const float* __restrict__ attn_mask,
                       const float* __restrict__ qkv_b,
                       const float* __restrict__ proj_b,
                       const float* __restrict__ bias_table,
                       const int*   __restrict__ rel_idx,
                       float* __restrict__ out)
{
    extern __shared__ uint2 smu[];
    uint2* XH = smu + O_X;     // x then q
    uint2* WH = smu + O_W;
    uint2* KH = smu + O_K;
    uint2* VT = smu + O_VT;
    uint2* AT = smu;           // attn overlay (R1+R2)
    uint2* OV = smu + O_K;     // overlay KH

    const int tid  = threadIdx.x;
    const int bx   = blockIdx.x;
    const int lane = tid & 31;
    const int wid  = tid >> 5;
    const int g    = lane >> 2;
    const int t    = lane & 3;

    // dense-GEMM roles: 8 m-tiles x 2 n-halves
    const int mt = wid >> 1, nh = wid & 1;
    const int r0 = mt * 16 + g, r1 = r0 + 8;
    const int ra = min(r0, 111), ra8 = min(r1, 111);
    const bool act = (mt < 7);
    const int win0 = (r0 >= 56), win1 = (r1 >= 56);
    const int i0 = r0 - 56 * win0, i1 = r1 - 56 * win1;
    const bool v0ok = act && (i0 < 49);
    const bool v1ok = act && (i1 < 49);
    const int wc = nh * 32 + g;

    // ---------------- phase 0: load+split x (2 windows); zero KH pads + VT ----------------
    for (int idx = tid; idx < 2 * 49 * 64; idx += NTHR) {
        int wloc = idx / 3136, rem = idx - wloc * 3136;
        int i = rem >> 6, u = rem & 63;
        const float* xg = x + ((size_t)(2 * bx + wloc) * 49 + i) * 128;
        float2 v = *(const float2*)(xg + 2 * u);
        XH[(wloc * 56 + i) * 68 + u] = split_pack(v.x, v.y);
    }
    for (int idx = tid; idx < 14 * 68; idx += NTHR) {
        int r = idx / 68, c = idx - r * 68;
        int row = (r < 7) ? (49 + r) : (98 + r);      // rows 49..55, 105..111
        KH[row * 68 + c] = make_uint2(0, 0);
    }
    for (int idx = tid; idx < 2 * 128 * VSTR; idx += NTHR)
        VT[idx] = make_uint2(0, 0);

    // ---------------- phase 1a: K and V chunks ----------------
    #pragma unroll 1
    for (int s = 0; s < 4; ++s) {
        const int ci = s + 2;                          // chunks 2,3 = k ; 4,5 = v
        __syncthreads();
        const uint2* gsrc = gW + (size_t)ci * 4096;
        for (int idx = tid; idx < 4096; idx += NTHR)
            WH[(idx >> 6) * 68 + (idx & 63)] = gsrc[idx];
        __syncthreads();
        if (!act) continue;

        float d[4][4] = {};
        mma_dense(XH, WH, d, ra, ra8, wc, t);

        if (s < 2) {
            #pragma unroll
            for (int nb = 0; nb < 4; ++nb) {
                int lc = nh * 32 + nb * 8 + 2 * t;
                int gc = (ci - 2) * 64 + lc;
                float b0 = qkv_b[128 + gc], b1 = qkv_b[129 + gc];
                int wcol = gc >> 1;
                if (v0ok) KH[r0 * 68 + wcol] = split_pack(d[nb][0] + b0, d[nb][1] + b1);
                if (v1ok) KH[r1 * 68 + wcol] = split_pack(d[nb][2] + b0, d[nb][3] + b1);
            }
        } else {
            // V: pair tokens via shfl (lane^4 flips g parity), store u2 into VT
            #pragma unroll
            for (int nb = 0; nb < 4; ++nb) {
                int lc = nh * 32 + nb * 8 + 2 * t;
                int c = (ci - 4) * 64 + lc;
                float b0 = qkv_b[256 + c], b1 = qkv_b[257 + c];
                #pragma unroll
                for (int rr = 0; rr < 2; ++rr) {
                    float vc  = d[nb][2 * rr]     + b0;
                    float vc1 = d[nb][2 * rr + 1] + b1;
                    float oc  = __shfl_xor_sync(0xffffffffu, vc, 4);
                    float oc1 = __shfl_xor_sync(0xffffffffu, vc1, 4);
                    int row = rr ? r1 : r0;
                    int wn = (row >= 56), il = row - 56 * wn;
                    if (!(g & 1) && il < 49) {
                        float e1 = (il + 1 < 49) ? oc  : 0.f;
                        float f1 = (il + 1 < 49) ? oc1 : 0.f;
                        int u = il >> 1;
                        VT[(wn * 128 + c)     * VSTR + u] = split_pack(vc,  e1);
                        VT[(wn * 128 + c + 1) * VSTR + u] = split_pack(vc1, f1);
                    }
                }
            }
        }
    }

    // ---------------- phase 1b: Q chunks (regs), then overwrite XH with q ----------------
    float dq0[4][4] = {}, dq1[4][4] = {};
    __syncthreads();
    for (int idx = tid; idx < 4096; idx += NTHR)
        WH[(idx >> 6) * 68 + (idx & 63)] = gW[idx];
    __syncthreads();
    if (act) mma_dense(XH, WH, dq0, ra, ra8, wc, t);
    __syncthreads();
    for (int idx = tid; idx < 4096; idx += NTHR)
        WH[(idx >> 6) * 68 + (idx & 63)] = gW[4096 + idx];
    __syncthreads();
    if (act) mma_dense(XH, WH, dq1, ra, ra8, wc, t);
    __syncthreads();                                   // all q-mma reads of XH done
    if (act) {
        #pragma unroll
        for (int nb = 0; nb < 4; ++nb) {
            int lc = nh * 32 + nb * 8 + 2 * t;
            {
                int gc = lc;
                float b0 = qkv_b[gc], b1 = qkv_b[gc + 1];
                int wcol = gc >> 1;
                if (v0ok) XH[r0 * 68 + wcol] =
                    split_pack((dq0[nb][0] + b0) * SCALE, (dq0[nb][1] + b1) * SCALE);
                if (v1ok) XH[r1 * 68 + wcol] =
                    split_pack((dq0[nb][2] + b0) * SCALE, (dq0[nb][3] + b1) * SCALE);
            }
            {
                int gc = 64 + lc;
                float b0 = qkv_b[gc], b1 = qkv_b[gc + 1];
                int wcol = gc >> 1;
                if (v0ok) XH[r0 * 68 + wcol] =
                    split_pack((dq1[nb][0] + b0) * SCALE, (dq1[nb][1] + b1) * SCALE);
                if (v1ok) XH[r1 * 68 + wcol] =
                    split_pack((dq1[nb][2] + b0) * SCALE, (dq1[nb][3] + b1) * SCALE);
            }
        }
    }
    __syncthreads();

    // ---------------- phase 2: QK^T (both tasks into regs) ----------------
    float d2[2][7][4];
    #pragma unroll
    for (int it = 0; it < 2; ++it) {
        int task = wid + 16 * it;
        int qwin = task >> 4, rem = task & 15, h = rem >> 2, qt = rem & 3;
        int l0 = qt * 16 + g;
        int qa0 = qwin * 56 + min(l0, 48);
        int qa1 = qwin * 56 + min(l0 + 8, 48);
        #pragma unroll
        for (int jb = 0; jb < 7; ++jb)
            #pragma unroll
            for (int e = 0; e < 4; ++e) d2[it][jb][e] = 0.f;
        #pragma unroll
        for (int kb = 0; kb < 2; ++kb) {
            int kw = h * 16 + kb * 8 + t;
            uint2 a0 = XH[qa0 * 68 + kw];
            uint2 a1 = XH[qa1 * 68 + kw];
            uint2 a2 = XH[qa0 * 68 + kw + 4];
            uint2 a3 = XH[qa1 * 68 + kw + 4];
            unsigned ah[4] = {a0.x, a1.x, a2.x, a3.x};
            unsigned al[4] = {a0.y, a1.y, a2.y, a3.y};
            #pragma unroll
            for (int jb = 0; jb < 7; ++jb) {
                int kr = qwin * 56 + jb * 8 + g;
                mma3(d2[it][jb], ah, al, KH[kr * 68 + kw], KH[kr * 68 + kw + 4]);
            }
        }
    }
    __syncthreads();    // q/k reads complete; attn region (R1+R2) now writable

    // ---------------- phase 3: bias+mask+softmax in regs, write packed attn ----------------
    #pragma unroll
    for (int it = 0; it < 2; ++it) {
        int task = wid + 16 * it;
        int qwin = task >> 4, rem = task & 15, h = rem >> 2, qt = rem & 3;
        const float* maskg = attn_mask + (size_t)((2 * bx + qwin) & 63) * (NTOK * NTOK);
        #pragma unroll
        for (int rr = 0; rr < 2; ++rr) {
            int li = qt * 16 + g + rr * 8;
            bool okr = (li < 49);
            float sv[14];
            float mx = -INFINITY;
            #pragma unroll
            for (int jb = 0; jb < 7; ++jb) {
                #pragma unroll
                for (int e = 0; e < 2; ++e) {
                    int j = jb * 8 + 2 * t + e;
                    float val = -INFINITY;
                    if (okr && j < 49) {
                        int ij = li * 49 + j;
                        val = d2[it][jb][rr * 2 + e]
                            + bias_table[rel_idx[ij] * 4 + h] + maskg[ij];
                    }
                    sv[jb * 2 + e] = val;
                    mx = fmaxf(mx, val);
                }
            }
            mx = fmaxf(mx, __shfl_xor_sync(0xffffffffu, mx, 1));
            mx = fmaxf(mx, __shfl_xor_sync(0xffffffffu, mx, 2));
            float sum = 0.f;
            #pragma unroll
            for (int n = 0; n < 14; ++n) { sv[n] = __expf(sv[n] - mx); sum += sv[n]; }
            sum += __shfl_xor_sync(0xffffffffu, sum, 1);
            sum += __shfl_xor_sync(0xffffffffu, sum, 2);
            float inv = 1.f / sum;
            if (okr) {
                uint2* arow = AT + ((size_t)(qwin * 4 + h) * 49 + li) * 32;
                #pragma unroll
                for (int jb = 0; jb < 7; ++jb)
                    arow[4 * jb + t] = split_pack(sv[2 * jb] * inv, sv[2 * jb + 1] * inv);
                arow[28 + t] = make_uint2(0, 0);        // zero pad cols 28..31
            }
        }
    }
    __syncthreads();

    // ---------------- phase 4: AV -> OV (overlay KH) ----------------
    #pragma unroll
    for (int it = 0; it < 2; ++it) {
        int task = wid + 16 * it;
        int qwin = task >> 4, rem = task & 15, h = rem >> 2, qt = rem & 3;
        int l0 = qt * 16 + g;
        const uint2* ab = AT + (size_t)(qwin * 4 + h) * 49 * 32;
        int qa0 = min(l0, 48), qa1 = min(l0 + 8, 48);
        float d[4][4] = {};
        #pragma unroll
        for (int kb = 0; kb < 4; ++kb) {
            int kw = kb * 8 + t;
            uint2 a0 = ab[qa0 * 32 + kw];
            uint2 a1 = ab[qa1 * 32 + kw];
            uint2 a2 = ab[qa0 * 32 + kw + 4];
            uint2 a3 = ab[qa1 * 32 + kw + 4];
            unsigned ah[4] = {a0.x, a1.x, a2.x, a3.x};
            unsigned al[4] = {a0.y, a1.y, a2.y, a3.y};
            #pragma unroll
            for (int nb = 0; nb < 4; ++nb) {
                int c = 32 * h + nb * 8 + g;
                mma3(d[nb], ah, al, VT[(qwin * 128 + c) * VSTR + kw],
                                    VT[(qwin * 128 + c) * VSTR + kw + 4]);
            }
        }
        #pragma unroll
        for (int nb = 0; nb < 4; ++nb) {
            int cw = 16 * h + nb * 4 + t;
            if (l0 < 49)
                OV[(qwin * 56 + l0) * 68 + cw] = split_pack(d[nb][0], d[nb][1]);
            if (l0 + 8 < 49)
                OV[(qwin * 56 + l0 + 8) * 68 + cw] = split_pack(d[nb][2], d[nb][3]);
        }
    }

    // ---------------- phase 5: proj GEMM (chunks 6,7) ----------------
    #pragma unroll 1
    for (int s = 0; s < 2; ++s) {
        __syncthreads();
        const uint2* gsrc = gW + (size_t)(6 + s) * 4096;
        for (int idx = tid; idx < 4096; idx += NTHR)
            WH[(idx >> 6) * 68 + (idx & 63)] = gsrc[idx];
        __syncthreads();
        if (!act) continue;

        float d[4][4] = {};
        mma_dense(OV, WH, d, ra, ra8, wc, t);

        #pragma unroll
        for (int nb = 0; nb < 4; ++nb) {
            int lc = nh * 32 + nb * 8 + 2 * t;
            int gc = s * 64 + lc;
            float b0 = proj_b[gc], b1 = proj_b[gc + 1];
            if (v0ok)
                *(float2*)(out + ((size_t)(2 * bx + win0) * 49 + i0) * 128 + gc)
                    = make_float2(d[nb][0] + b0, d[nb][1] + b1);
            if (v1ok)
                *(float2*)(out + ((size_t)(2 * bx + win1) * 49 + i1) * 128 + gc)
                    = make_float2(d[nb][2] + b0, d[nb][3] + b1);
        }
    }
}

extern "C" void kernel_launch(void* const* d_in, const int* in_sizes, int n_in,
                              void* d_out, int out_size)
{
    const float* x          = (const float*)d_in[0];
    const float* attn_mask  = (const float*)d_in[1];
    const float* qkv_w      = (const float*)d_in[2];
    const float* qkv_b      = (const float*)d_in[3];
    const float* proj_w     = (const float*)d_in[4];
    const float* proj_b     = (const float*)d_in[5];
    const float* bias_table = (const float*)d_in[6];
    const int*   rel_idx    = (const int*)d_in[7];
    float* out = (float*)d_out;

    prep_kernel<<<64, 512>>>(qkv_w, proj_w);

    const int smem_bytes = SM_U2 * sizeof(uint2);   // 231,424 B
    cudaFuncSetAttribute(wmsa_fused_kernel,
                         cudaFuncAttributeMaxDynamicSharedMemorySize, smem_bytes);

    const int n_windows = in_sizes[0] / (NTOK * 128);   // 4096
    wmsa_fused_kernel<<<n_windows / 2, NTHR, smem_bytes>>>(
        x, attn_mask, qkv_b, proj_b, bias_table, rel_idx, out);
}